// round 16
// baseline (speedup 1.0000x reference)
#include <cuda_runtime.h>

#define VOCAB 9
#define D     4
#define S     16384
#define NBLK  64

// Packed shared weight layout (121 floats):
#define W_EMB   0
#define W_PROJW 36
#define W_PROJB 52
#define W_FORWW 56
#define W_FORWB 72
#define W_PRJW  76
#define W_PRJB  112
#define W_TOTAL 121

// Self-validating count words: word w holds counters 3w..3w+2 in 15-bit
// fields (global max 16384 < 32767) and an arrive count at bits 45-51.
// A word whose arrive field reads NBLK is final. Zero at load; last
// finishing block resets for graph replays.
__device__ unsigned long long g_w[3];
__device__ unsigned           g_done;

__device__ __forceinline__ const float* wsrc(
    int q,
    const float* emb, const float* proj_w, const float* proj_b,
    const float* forw_w, const float* forw_b,
    const float* prj_w, const float* prj_b)
{
    if      (q < W_PROJW) return emb    + (q - W_EMB);
    else if (q < W_PROJB) return proj_w + (q - W_PROJW);
    else if (q < W_FORWW) return proj_b + (q - W_PROJB);
    else if (q < W_FORWB) return forw_w + (q - W_FORWW);
    else if (q < W_PRJW)  return forw_b + (q - W_FORWB);
    else if (q < W_PRJB)  return prj_w  + (q - W_PRJW);
    else                  return prj_b  + (q - W_PRJB);
}

// Table threads (tid < VOCAB): count-independent precompute, poll the 3
// fused words, finish the 9x9 probability table into sp.
__device__ __forceinline__ void table_poll_finish(
    int tid, const float* sw, const float (*h0s)[D], float* sp)
{
    if (tid >= VOCAB) return;

    float hv0 = h0s[tid][0], hv1 = h0s[tid][1],
          hv2 = h0s[tid][2], hv3 = h0s[tid][3];
    float sc[VOCAB];
    float m = -3.4e38f;
    #pragma unroll
    for (int u = 0; u < VOCAB; u++) {
        float s = hv0 * h0s[u][0] + hv1 * h0s[u][1]
                + hv2 * h0s[u][2] + hv3 * h0s[u][3];
        sc[u] = s;
        m = fmaxf(m, s);
    }
    float eu[VOCAB];
    #pragma unroll
    for (int u = 0; u < VOCAB; u++)
        eu[u] = __expf(sc[u] - m);

    // poll until every arrive field shows NBLK (co-resident => safe)
    volatile unsigned long long* gw = g_w;
    unsigned long long w0, w1, w2;
    do {
        w0 = gw[0]; w1 = gw[1]; w2 = gw[2];
    } while (((w0 >> 45) & 0x7F) < (unsigned)NBLK ||
             ((w1 >> 45) & 0x7F) < (unsigned)NBLK ||
             ((w2 >> 45) & 0x7F) < (unsigned)NBLK);

    int cu[VOCAB];
    #pragma unroll
    for (int q = 0; q < VOCAB; q++) {
        unsigned long long w = (q < 3) ? w0 : (q < 6) ? w1 : w2;
        cu[q] = (int)((w >> (15 * (q % 3))) & 0x7FFFULL);
    }

    // grouped softmax-weighted sum: attn @ h (exact regrouping by token)
    float wsum = 0.f, a0 = 0.f, a1 = 0.f, a2 = 0.f, a3 = 0.f;
    #pragma unroll
    for (int u = 0; u < VOCAB; u++) {
        float e = eu[u] * (float)cu[u];
        wsum += e;
        a0 += e * h0s[u][0];
        a1 += e * h0s[u][1];
        a2 += e * h0s[u][2];
        a3 += e * h0s[u][3];
    }
    float inv = 1.0f / wsum;
    float r0 = fmaxf(0.f, a0 * inv), r1 = fmaxf(0.f, a1 * inv);
    float r2 = fmaxf(0.f, a2 * inv), r3 = fmaxf(0.f, a3 * inv);

    float h2[D];
    #pragma unroll
    for (int d = 0; d < D; d++) {
        h2[d] = sw[W_FORWB + d]
              + sw[W_FORWW + d * D + 0] * r0
              + sw[W_FORWW + d * D + 1] * r1
              + sw[W_FORWW + d * D + 2] * r2
              + sw[W_FORWW + d * D + 3] * r3;
    }

    float lg[VOCAB];
    float m2 = -3.4e38f;
    #pragma unroll
    for (int c = 0; c < VOCAB; c++) {
        float a = sw[W_PRJB + c];
        #pragma unroll
        for (int k = 0; k < D; k++)
            a += sw[W_PRJW + c * D + k] * h2[k];
        lg[c] = a;
        m2 = fmaxf(m2, a);
    }
    float zsum = 0.f;
    #pragma unroll
    for (int c = 0; c < VOCAB; c++) {
        lg[c] = __expf(lg[c] - m2);
        zsum += lg[c];
    }
    float zinv = 1.0f / zsum;
    #pragma unroll
    for (int c = 0; c < VOCAB; c++)
        sp[tid * VOCAB + c] = lg[c] * zinv;
}

// ---------------------------------------------------------------------------
// GENERIC kernel (64x64): warp-local detection, speculative L2 prefetch of
// the (possibly nonexistent) upper half — prefetch.global.L2 is non-faulting
// on invalid addresses, so it is safe under the int32 layout and converts the
// int64 path's second DRAM latency into an L2 hit. Fused-word posting,
// overlapped reset.
// ---------------------------------------------------------------------------
__global__ void __launch_bounds__(64) bert_fused_kernel(
    const int* __restrict__ x32,
    const float* __restrict__ emb,   const float* __restrict__ proj_w,
    const float* __restrict__ proj_b,const float* __restrict__ forw_w,
    const float* __restrict__ forw_b,const float* __restrict__ prj_w,
    const float* __restrict__ prj_b, float4* __restrict__ out4)
{
    __shared__ int   warp_cnt[2][VOCAB];
    __shared__ float sw[W_TOTAL + 7];
    __shared__ float h0s[VOCAB][D];
    __shared__ float sp[VOCAB * VOCAB];

    const int tid  = threadIdx.x;
    const int wid  = tid >> 5;
    const int lane = tid & 31;
    const int t    = blockIdx.x * 64 + tid;       // 0..4095
    const int4* p4 = (const int4*)x32;

    // ---- speculative L2 prefetch of the upper half (non-faulting even if
    //      the int32 layout makes this address range invalid; under the real
    //      int64 layout it is in-bounds) ----
    asm volatile("prefetch.global.L2 [%0];" :: "l"(p4 + 4096 + t));

    float wr0 = 0.f, wr1 = 0.f;
    if (tid < W_TOTAL)
        wr0 = __ldg(wsrc(tid, emb, proj_w, proj_b, forw_w, forw_b, prj_w, prj_b));
    if (tid + 64 < W_TOTAL)
        wr1 = __ldg(wsrc(tid + 64, emb, proj_w, proj_b, forw_w, forw_b, prj_w, prj_b));

    int4 pr = __ldg(p4 + t);                      // in-bounds both layouts

    // WARP-LOCAL detection: 64 odd words per warp, fp-prob (1/9)^64 ~ 0.
    bool okb = (pr.y == 0) && (pr.w == 0)
            && ((unsigned)pr.x < VOCAB) && ((unsigned)pr.z < VOCAB);
    const int is64 = (__all_sync(0xffffffffu, okb) != 0);

    unsigned long long acc = (1ULL << (7 * pr.x)) + (1ULL << (7 * pr.z));

    int  vals[4];
    int4 up, pl0, pl1;
    if (is64) {                 // gated loads: upper now L2-warm; payload in
        up  = __ldg(p4 + 4096 + t);   // the probe-warmed lower half
        pl0 = __ldg(p4 + 2 * t);
        pl1 = __ldg(p4 + 2 * t + 1);
    } else {
        acc += (1ULL << (7 * pr.y)) + (1ULL << (7 * pr.w));
        vals[0] = pr.x; vals[1] = pr.y; vals[2] = pr.z; vals[3] = pr.w;
    }

    // sw store + barrier hidden under the gated-load latency
    if (tid < W_TOTAL)      sw[tid]      = wr0;
    if (tid + 64 < W_TOTAL) sw[tid + 64] = wr1;
    __syncthreads();                              // B1: sw

    // h0 math also overlaps the gated-load latency (threads 0..35)
    if (tid < VOCAB * D) {
        int vv = tid / D, d = tid % D;
        float a = sw[W_PROJB + d];
        #pragma unroll
        for (int k = 0; k < D; k++)
            a += sw[W_EMB + vv * D + k] * sw[W_PROJW + d * D + k];
        h0s[vv][d] = a;
    }

    if (is64) {
        acc += (1ULL << (7 * up.x)) + (1ULL << (7 * up.z));
        vals[0] = pl0.x; vals[1] = pl0.z; vals[2] = pl1.x; vals[3] = pl1.z;
    }

    #pragma unroll
    for (int q = 0; q < VOCAB; q++) {
        unsigned c  = (unsigned)((acc >> (7 * q)) & 127ULL);
        unsigned ws = __reduce_add_sync(0xffffffffu, c);
        if (lane == 0) warp_cnt[wid][q] = (int)ws;
    }
    __syncthreads();                              // B2: warp_cnt, h0s

    // post fused words (threads 0..2) — single concurrent atomic round
    if (tid < 3) {
        unsigned long long pack = 1ULL << 45;
        #pragma unroll
        for (int k = 0; k < 3; k++) {
            int q  = tid * 3 + k;
            int bc = warp_cnt[0][q] + warp_cnt[1][q];
            pack |= (unsigned long long)bc << (15 * k);
        }
        atomicAdd(&g_w[tid], pack);
    }

    table_poll_finish(tid, sw, h0s, sp);
    __syncthreads();                              // B3: sp

    // overlap reset chain with scatter: atomic issued, return consumed later
    unsigned done_r = 0xFFFFFFFFu;
    if (tid == 0) done_r = atomicAdd(&g_done, 1u);

    // scatter: thread t owns output rows 4t..4t+3 (9 aligned float4)
    float4* o = out4 + (size_t)t * 9;
    #pragma unroll
    for (int k = 0; k < 9; k++) {
        float4 f;
        f.x = sp[vals[(4 * k + 0) / 9] * VOCAB + (4 * k + 0) % 9];
        f.y = sp[vals[(4 * k + 1) / 9] * VOCAB + (4 * k + 1) % 9];
        f.z = sp[vals[(4 * k + 2) / 9] * VOCAB + (4 * k + 2) % 9];
        f.w = sp[vals[(4 * k + 3) / 9] * VOCAB + (4 * k + 3) % 9];
        o[k] = f;
    }

    // replay-safe reset: last finishing block zeroes the words (every
    // block's g_w reads completed before its g_done increment).
    if (tid == 0 && done_r == (unsigned)(NBLK - 1)) {
        g_w[0] = 0ULL; g_w[1] = 0ULL; g_w[2] = 0ULL;
        __threadfence();
        g_done = 0u;
    }
}

extern "C" void kernel_launch(void* const* d_in, const int* in_sizes, int n_in,
                              void* d_out, int out_size)
{
    const int*   x      = (const int*)d_in[0];
    const float* emb    = (const float*)d_in[1];
    const float* proj_w = (const float*)d_in[2];
    const float* proj_b = (const float*)d_in[3];
    const float* forw_w = (const float*)d_in[4];
    const float* forw_b = (const float*)d_in[5];
    const float* prj_w  = (const float*)d_in[6];
    const float* prj_b  = (const float*)d_in[7];

    bert_fused_kernel<<<NBLK, 64>>>(x, emb, proj_w, proj_b,
                                    forw_w, forw_b, prj_w, prj_b,
                                    (float4*)d_out);
    (void)in_sizes; (void)n_in; (void)out_size;
}

// round 17
// speedup vs baseline: 1.0332x; 1.0332x over previous
#include <cuda_runtime.h>

#define VOCAB 9
#define D     4
#define S     16384
#define NBLK  64
#define NPOST (2 * NBLK)   // per-WARP posting: 128 arrive increments total

// Packed shared weight layout (121 floats):
#define W_EMB   0
#define W_PROJW 36
#define W_PROJB 52
#define W_FORWW 56
#define W_FORWB 72
#define W_PRJW  76
#define W_PRJB  112
#define W_TOTAL 121

// Self-validating count words: word w holds counters 3w..3w+2 in 15-bit
// fields (global max 16384 < 32767) and an arrive count at bits 45+
// (max 128 warp-posts). A word whose arrive field reads NPOST is final.
// Zero at load; last finishing block resets for graph replays.
__device__ unsigned long long g_w[3];
__device__ unsigned           g_done;

__device__ __forceinline__ const float* wsrc(
    int q,
    const float* emb, const float* proj_w, const float* proj_b,
    const float* forw_w, const float* forw_b,
    const float* prj_w, const float* prj_b)
{
    if      (q < W_PROJW) return emb    + (q - W_EMB);
    else if (q < W_PROJB) return proj_w + (q - W_PROJW);
    else if (q < W_FORWW) return proj_b + (q - W_PROJB);
    else if (q < W_FORWB) return forw_w + (q - W_FORWW);
    else if (q < W_PRJW)  return forw_b + (q - W_FORWB);
    else if (q < W_PRJB)  return prj_w  + (q - W_PRJW);
    else                  return prj_b  + (q - W_PRJB);
}

// ---------------------------------------------------------------------------
// 64x64, ONE block barrier.
//  Warp 0 owns weights/h0/table (warp-private sync only); each warp posts
//  its own fused count words straight from REDUX broadcast (no staging
//  barrier). g_done posted as soon as warp 0's table threads finish reading
//  g_w, overlapping the final barrier + scatter.
// ---------------------------------------------------------------------------
__global__ void __launch_bounds__(64) bert_fused_kernel(
    const int* __restrict__ x32,
    const float* __restrict__ emb,   const float* __restrict__ proj_w,
    const float* __restrict__ proj_b,const float* __restrict__ forw_w,
    const float* __restrict__ forw_b,const float* __restrict__ prj_w,
    const float* __restrict__ prj_b, float4* __restrict__ out4)
{
    __shared__ float sw[W_TOTAL + 7];
    __shared__ float h0s[VOCAB][D];
    __shared__ float sp[VOCAB * VOCAB];

    const int tid  = threadIdx.x;
    const int wid  = tid >> 5;
    const int lane = tid & 31;
    const int t    = blockIdx.x * 64 + tid;       // 0..4095
    const int4* p4 = (const int4*)x32;

    // speculative L2 prefetch of the upper half (non-faulting; in-bounds
    // under the real int64 layout)
    asm volatile("prefetch.global.L2 [%0];" :: "l"(p4 + 4096 + t));

    // ---- warp 0 loads ALL weights (4 per lane) ----
    float w0 = 0.f, w1 = 0.f, w2 = 0.f, w3 = 0.f;
    if (wid == 0) {
        w0 = __ldg(wsrc(lane,      emb, proj_w, proj_b, forw_w, forw_b, prj_w, prj_b));
        w1 = __ldg(wsrc(lane + 32, emb, proj_w, proj_b, forw_w, forw_b, prj_w, prj_b));
        w2 = __ldg(wsrc(lane + 64, emb, proj_w, proj_b, forw_w, forw_b, prj_w, prj_b));
        if (lane < W_TOTAL - 96)
            w3 = __ldg(wsrc(lane + 96, emb, proj_w, proj_b, forw_w, forw_b, prj_w, prj_b));
    }

    // ---- probe (in-bounds under both layouts) ----
    int4 pr = __ldg(p4 + t);

    // warp-local detection: 64 odd words/warp, fp-prob (1/9)^64 ~ 0
    bool okb = (pr.y == 0) && (pr.w == 0)
            && ((unsigned)pr.x < VOCAB) && ((unsigned)pr.z < VOCAB);
    const int is64 = (__all_sync(0xffffffffu, okb) != 0);

    unsigned long long acc = (1ULL << (7 * pr.x)) + (1ULL << (7 * pr.z));

    int  vals[4];
    int4 up, pl0, pl1;
    if (is64) {
        up  = __ldg(p4 + 4096 + t);
        pl0 = __ldg(p4 + 2 * t);
        pl1 = __ldg(p4 + 2 * t + 1);
    } else {
        acc += (1ULL << (7 * pr.y)) + (1ULL << (7 * pr.w));
        vals[0] = pr.x; vals[1] = pr.y; vals[2] = pr.z; vals[3] = pr.w;
    }

    // warp 0 stages weights while gated loads fly
    if (wid == 0) {
        sw[lane]      = w0;
        sw[lane + 32] = w1;
        sw[lane + 64] = w2;
        if (lane < W_TOTAL - 96) sw[lane + 96] = w3;
    }

    if (is64) {
        acc += (1ULL << (7 * up.x)) + (1ULL << (7 * up.z));
        vals[0] = pl0.x; vals[1] = pl0.z; vals[2] = pl1.x; vals[3] = pl1.z;
    }

    // ---- REDUX: broadcast warp sums to every lane ----
    unsigned wsum[VOCAB];
    #pragma unroll
    for (int q = 0; q < VOCAB; q++)
        wsum[q] = __reduce_add_sync(0xffffffffu,
                                    (unsigned)((acc >> (7 * q)) & 127ULL));

    // ---- post per-WARP fused words (lanes 0..2 of each warp) ----
    if (lane < 3) {
        unsigned long long pack = 1ULL << 45;     // arrive += 1 (target 128)
        #pragma unroll
        for (int k = 0; k < 3; k++)
            pack |= (unsigned long long)wsum[lane * 3 + k] << (15 * k);
        atomicAdd(&g_w[lane], pack);
    }

    unsigned done_r = 0xFFFFFFFFu;

    if (wid == 0) {
        __syncwarp();                             // sw visible in warp 0

        // h0[v][d]: 36 jobs over 32 lanes (lanes 0-3 take a second job)
        #pragma unroll
        for (int rep = 0; rep < 2; rep++) {
            int job = lane + rep * 32;
            if (job < VOCAB * D) {
                int vv = job / D, d = job % D;
                float a = sw[W_PROJB + d];
                #pragma unroll
                for (int k = 0; k < D; k++)
                    a += sw[W_EMB + vv * D + k] * sw[W_PROJW + d * D + k];
                h0s[vv][d] = a;
            }
        }
        __syncwarp();                             // h0s visible in warp 0

        // ---- table threads: precompute, poll, finish 9x9 table ----
        if (lane < VOCAB) {
            float hv0 = h0s[lane][0], hv1 = h0s[lane][1],
                  hv2 = h0s[lane][2], hv3 = h0s[lane][3];
            float sc[VOCAB];
            float m = -3.4e38f;
            #pragma unroll
            for (int u = 0; u < VOCAB; u++) {
                float s = hv0 * h0s[u][0] + hv1 * h0s[u][1]
                        + hv2 * h0s[u][2] + hv3 * h0s[u][3];
                sc[u] = s;
                m = fmaxf(m, s);
            }
            float eu[VOCAB];
            #pragma unroll
            for (int u = 0; u < VOCAB; u++)
                eu[u] = __expf(sc[u] - m);

            // poll until every arrive field shows NPOST (co-resident => safe)
            volatile unsigned long long* gw = g_w;
            unsigned long long wd0, wd1, wd2;
            do {
                wd0 = gw[0]; wd1 = gw[1]; wd2 = gw[2];
            } while ((unsigned)(wd0 >> 45) < (unsigned)NPOST ||
                     (unsigned)(wd1 >> 45) < (unsigned)NPOST ||
                     (unsigned)(wd2 >> 45) < (unsigned)NPOST);

            int cu[VOCAB];
            #pragma unroll
            for (int q = 0; q < VOCAB; q++) {
                unsigned long long w = (q < 3) ? wd0 : (q < 6) ? wd1 : wd2;
                cu[q] = (int)((w >> (15 * (q % 3))) & 0x7FFFULL);
            }

            // grouped softmax-weighted sum (exact regrouping by token)
            float wsumf = 0.f, a0 = 0.f, a1 = 0.f, a2 = 0.f, a3 = 0.f;
            #pragma unroll
            for (int u = 0; u < VOCAB; u++) {
                float e = eu[u] * (float)cu[u];
                wsumf += e;
                a0 += e * h0s[u][0];
                a1 += e * h0s[u][1];
                a2 += e * h0s[u][2];
                a3 += e * h0s[u][3];
            }
            float inv = 1.0f / wsumf;
            float r0 = fmaxf(0.f, a0 * inv), r1 = fmaxf(0.f, a1 * inv);
            float r2 = fmaxf(0.f, a2 * inv), r3 = fmaxf(0.f, a3 * inv);

            float h2[D];
            #pragma unroll
            for (int d = 0; d < D; d++) {
                h2[d] = sw[W_FORWB + d]
                      + sw[W_FORWW + d * D + 0] * r0
                      + sw[W_FORWW + d * D + 1] * r1
                      + sw[W_FORWW + d * D + 2] * r2
                      + sw[W_FORWW + d * D + 3] * r3;
            }

            float lg[VOCAB];
            float m2 = -3.4e38f;
            #pragma unroll
            for (int c = 0; c < VOCAB; c++) {
                float a = sw[W_PRJB + c];
                #pragma unroll
                for (int k = 0; k < D; k++)
                    a += sw[W_PRJW + c * D + k] * h2[k];
                lg[c] = a;
                m2 = fmaxf(m2, a);
            }
            float zsum = 0.f;
            #pragma unroll
            for (int c = 0; c < VOCAB; c++) {
                lg[c] = __expf(lg[c] - m2);
                zsum += lg[c];
            }
            float zinv = 1.0f / zsum;
            #pragma unroll
            for (int c = 0; c < VOCAB; c++)
                sp[lane * VOCAB + c] = lg[c] * zinv;
        }
        __syncwarp();                 // table threads' g_w reads complete

        // post g_done early: overlaps barrier + scatter
        if (lane == 0) done_r = atomicAdd(&g_done, 1u);
    }

    __syncthreads();                  // ONLY block barrier: sp visible

    // ---- scatter: thread t owns output rows 4t..4t+3 (9 float4) ----
    float4* o = out4 + (size_t)t * 9;
    #pragma unroll
    for (int k = 0; k < 9; k++) {
        float4 f;
        f.x = sp[vals[(4 * k + 0) / 9] * VOCAB + (4 * k + 0) % 9];
        f.y = sp[vals[(4 * k + 1) / 9] * VOCAB + (4 * k + 1) % 9];
        f.z = sp[vals[(4 * k + 2) / 9] * VOCAB + (4 * k + 2) % 9];
        f.w = sp[vals[(4 * k + 3) / 9] * VOCAB + (4 * k + 3) % 9];
        o[k] = f;
    }

    // replay-safe reset: last finishing block zeroes the words (g_done
    // increments only after that block's g_w reads completed).
    if (tid == 0 && done_r == (unsigned)(NBLK - 1)) {
        g_w[0] = 0ULL; g_w[1] = 0ULL; g_w[2] = 0ULL;
        __threadfence();
        g_done = 0u;
    }
}

extern "C" void kernel_launch(void* const* d_in, const int* in_sizes, int n_in,
                              void* d_out, int out_size)
{
    const int*   x      = (const int*)d_in[0];
    const float* emb    = (const float*)d_in[1];
    const float* proj_w = (const float*)d_in[2];
    const float* proj_b = (const float*)d_in[3];
    const float* forw_w = (const float*)d_in[4];
    const float* forw_b = (const float*)d_in[5];
    const float* prj_w  = (const float*)d_in[6];
    const float* prj_b  = (const float*)d_in[7];

    bert_fused_kernel<<<NBLK, 64>>>(x, emb, proj_w, proj_b,
                                    forw_w, forw_b, prj_w, prj_b,
                                    (float4*)d_out);
    (void)in_sizes; (void)n_in; (void)out_size;
}